// round 16
// baseline (speedup 1.0000x reference)
#include <cuda_runtime.h>
#include <cuda_fp16.h>
#include <math.h>
#include <cstdint>

#define B_SZ   4
#define SEQ    2048
#define DMODEL 1024
#define NH     16
#define DH     64
#define ROWS   (B_SZ*SEQ)     // 8192
#define N_QKV  (3*DMODEL)     // 3072

// Scratch (allocation-free: device globals)
__device__ __half g_Qh[B_SZ*NH*SEQ*DH];  // fp16(Q), [bh][s][d]
__device__ __half g_Kh[B_SZ*NH*SEQ*DH];  // fp16(K), [bh][s][d]
__device__ __half g_Vh[B_SZ*NH*SEQ*DH];  // fp16(V), TRANSPOSED [bh][d][s]
__device__ __half g_Oh[ROWS*DMODEL];     // attention out fp16 (GEMM2 A)
__device__ __half g_xh[ROWS*DMODEL];     // fp16(x), [m][k]
__device__ __half g_w1t[N_QKV*DMODEL];   // fp16(w_in^T), [n][k]
__device__ __half g_w2t[DMODEL*DMODEL];  // fp16(w_out^T), [n][k]

// ============================================================================
// Helpers
// ============================================================================
__device__ __forceinline__ uint32_t pack_h2(float x, float y) {
    __half2 h = __floats2half2_rn(x, y);
    return *reinterpret_cast<uint32_t*>(&h);
}
// 2^x for a pair of floats -> packed fp16x2 (one cvt + one MUFU)
__device__ __forceinline__ uint32_t ex2_h2(float x, float y) {
    uint32_t h = pack_h2(x, y);
    uint32_t r;
    asm("ex2.approx.f16x2 %0, %1;" : "=r"(r) : "r"(h));
    return r;
}
__device__ __forceinline__ float ex2f(float x) {
    float r; asm("ex2.approx.f32 %0, %1;" : "=f"(r) : "f"(x)); return r;
}
__device__ __forceinline__ void mma_f16(float c[4],
    uint32_t a0, uint32_t a1, uint32_t a2, uint32_t a3,
    uint32_t b0, uint32_t b1)
{
    asm volatile(
        "mma.sync.aligned.m16n8k16.row.col.f32.f16.f16.f32 "
        "{%0,%1,%2,%3}, {%4,%5,%6,%7}, {%8,%9}, {%0,%1,%2,%3};"
        : "+f"(c[0]), "+f"(c[1]), "+f"(c[2]), "+f"(c[3])
        : "r"(a0), "r"(a1), "r"(a2), "r"(a3), "r"(b0), "r"(b1));
}
__device__ __forceinline__ uint32_t smem_u32(const void* p) {
    uint32_t a;
    asm("{ .reg .u64 t; cvta.to.shared.u64 t, %1; cvt.u32.u64 %0, t; }"
        : "=r"(a) : "l"(p));
    return a;
}
#define LDSM_X4(r0, r1, r2, r3, addr) \
    asm volatile("ldmatrix.sync.aligned.m8n8.x4.shared.b16 {%0,%1,%2,%3}, [%4];" \
        : "=r"(r0), "=r"(r1), "=r"(r2), "=r"(r3) : "r"(addr))
#define CP_ASYNC16(dst_u32, src_ptr) \
    asm volatile("cp.async.cg.shared.global [%0], [%1], 16;" \
                 :: "r"(dst_u32), "l"(src_ptr) : "memory")
#define CP_COMMIT  asm volatile("cp.async.commit_group;" ::: "memory")
#define CP_WAIT0   asm volatile("cp.async.wait_group 0;" ::: "memory")
#define CP_WAIT1   asm volatile("cp.async.wait_group 1;" ::: "memory")

#define H_ONES 0x3C003C00u   // half2(1.0, 1.0)

// ============================================================================
// Pre-kernels: fp16 convert (x) and transpose+convert (weights)
// ============================================================================
__global__ __launch_bounds__(256) void cvt_h_kernel(
    const float4* __restrict__ src, uint2* __restrict__ dst, int n4)
{
    int i = blockIdx.x * blockDim.x + threadIdx.x;
    if (i < n4) {
        float4 v = src[i];
        uint2 o;
        o.x = pack_h2(v.x, v.y);
        o.y = pack_h2(v.z, v.w);
        dst[i] = o;
    }
}

// dst[n][k] = fp16(src[k][n]);  K,N multiples of 32
__global__ __launch_bounds__(256) void transp_h_kernel(
    const float* __restrict__ src, __half* __restrict__ dst, int K, int N)
{
    __shared__ float tile[32][33];
    int k0 = blockIdx.y * 32, n0 = blockIdx.x * 32;
    int tx = threadIdx.x & 31, ty = threadIdx.x >> 5;   // 32 x 8
#pragma unroll
    for (int i = 0; i < 32; i += 8)
        tile[ty + i][tx] = src[(size_t)(k0 + ty + i) * N + n0 + tx];
    __syncthreads();
#pragma unroll
    for (int i = 0; i < 32; i += 8)
        dst[(size_t)(n0 + ty + i) * K + k0 + tx] = __float2half_rn(tile[tx][ty + i]);
}

// ============================================================================
// fp16 mma.sync GEMM: C[M,N] = A[M,1024] @ Wt[N,1024]^T + bias
// CTA 128x128, 256 thr (8 warps of 64x32), K-chunk 64, 2-slot ring,
// ONE wait_group0 + ONE barrier per chunk (16 total).
// mode 0: scatter (Q/K -> fp16 [bh][s][d], V -> fp16 transposed [bh][d][s])
// mode 1: Cout fp32 row-major
// ============================================================================
#define GROW_B   144                   // bytes per tile row (64 halves + pad)
#define GTILE_B  (128 * GROW_B)        // 18432 B per matrix tile
#define GSTAGE_B (2 * GTILE_B)         // 36864 B per stage (A + B)
#define GSM_BYTES (2 * GSTAGE_B)       // 73728 B

__global__ __launch_bounds__(256, 2) void gemm_h_kernel(
    const __half* __restrict__ A,      // [M,1024]
    const __half* __restrict__ Wt,     // [N,1024]
    const float* __restrict__ bias,
    float* __restrict__ Cout,
    int mode)
{
    extern __shared__ char smc[];
    uint32_t smb = smem_u32(smc);
    int tid  = threadIdx.x;
    int wid  = tid >> 5, lane = tid & 31;
    int m0 = blockIdx.y * 128, n0 = blockIdx.x * 128;
    int warp_m = (wid & 1) * 64;
    int warp_n = (wid >> 1) * 32;

    // loader: 2 threads per row, 64 B each
    const __half* a_src = A + (size_t)(m0 + (tid >> 1)) * DMODEL + (tid & 1) * 32;
    const __half* b_src = Wt + (size_t)(n0 + (tid >> 1)) * DMODEL + (tid & 1) * 32;
    uint32_t a_dst = smb + (tid >> 1) * GROW_B + (tid & 1) * 64;
    uint32_t b_dst = a_dst + GTILE_B;

    auto load_stage = [&](int s, int c) {
        int kc = c * 64;
        uint32_t so = s * GSTAGE_B;
#pragma unroll
        for (int q = 0; q < 4; q++) {
            CP_ASYNC16(a_dst + so + q * 16, a_src + kc + q * 8);
            CP_ASYNC16(b_dst + so + q * 16, b_src + kc + q * 8);
        }
    };

    float acc[4][4][4];
#pragma unroll
    for (int i = 0; i < 4; i++)
#pragma unroll
        for (int j = 0; j < 4; j++)
#pragma unroll
            for (int k = 0; k < 4; k++) acc[i][j][k] = 0.f;

    // ldmatrix lane addresses (byte offsets within a stage)
    int lrow = lane & 7, lt = lane >> 3;
    uint32_t aA[4], bA[2];
#pragma unroll
    for (int mt = 0; mt < 4; mt++)
        aA[mt] = smb + (warp_m + mt * 16 + lrow + (lt & 1) * 8) * GROW_B
               + (lt >> 1) * 16;
#pragma unroll
    for (int p = 0; p < 2; p++)
        bA[p] = smb + GTILE_B
              + (warp_n + p * 16 + lrow + (lt >> 1) * 8) * GROW_B + (lt & 1) * 16;

    load_stage(0, 0); CP_COMMIT;

    for (int c = 0; c < 16; c++) {
        uint32_t so = (c & 1) * GSTAGE_B;
        CP_WAIT0;                 // chunk c resident (only pending group)
        __syncthreads();          // visibility + slot (c+1)&1 free (chunk c-1 done)
        if (c + 1 < 16) load_stage((c + 1) & 1, c + 1);
        CP_COMMIT;

#pragma unroll
        for (int step = 0; step < 4; step++) {
            uint32_t kbb = so + step * 32;
            uint32_t af[4][4], bf[2][4];
#pragma unroll
            for (int mt = 0; mt < 4; mt++)
                LDSM_X4(af[mt][0], af[mt][1], af[mt][2], af[mt][3], aA[mt] + kbb);
#pragma unroll
            for (int p = 0; p < 2; p++)
                LDSM_X4(bf[p][0], bf[p][1], bf[p][2], bf[p][3], bA[p] + kbb);
#pragma unroll
            for (int mt = 0; mt < 4; mt++)
#pragma unroll
                for (int p = 0; p < 2; p++) {
                    mma_f16(acc[mt][2 * p], af[mt][0], af[mt][1], af[mt][2], af[mt][3],
                            bf[p][0], bf[p][1]);
                    mma_f16(acc[mt][2 * p + 1], af[mt][0], af[mt][1], af[mt][2], af[mt][3],
                            bf[p][2], bf[p][3]);
                }
        }
        __syncthreads();          // all warps done reading slot c&1 before refill
    }

    int crow = lane >> 2, ccol2 = (lane & 3) * 2;
#pragma unroll
    for (int mt = 0; mt < 4; mt++) {
#pragma unroll
        for (int nt = 0; nt < 4; nt++) {
            int n = n0 + warp_n + nt * 8 + ccol2;
            float bx = bias[n], by = bias[n + 1];
#pragma unroll
            for (int half = 0; half < 2; half++) {
                int m = m0 + warp_m + mt * 16 + crow + half * 8;
                float2 v;
                v.x = acc[mt][nt][half * 2 + 0] + bx;
                v.y = acc[mt][nt][half * 2 + 1] + by;
                if (mode == 1) {
                    *(float2*)(Cout + (size_t)m * DMODEL + n) = v;
                } else {
                    int b = m >> 11, srow = m & (SEQ - 1);
                    int chunk = n >> 10;
                    int cc = n & (DMODEL - 1);
                    int h = cc >> 6, d0 = cc & (DH - 1);
                    if (chunk == 2) {        // V -> fp16, transposed [bh][d][s]
                        size_t base = ((size_t)(b << 4) + h) * DH;
                        g_Vh[(base + d0) * SEQ + srow]     = __float2half_rn(v.x);
                        g_Vh[(base + d0 + 1) * SEQ + srow] = __float2half_rn(v.y);
                    } else {                 // K or Q -> fp16 [bh][s][d]
                        size_t off = (((size_t)(b << 4) + h) * SEQ + srow) * DH + d0;
                        uint32_t pk = pack_h2(v.x, v.y);
                        if (chunk == 0) *(uint32_t*)(g_Kh + off) = pk;
                        else            *(uint32_t*)(g_Qh + off) = pk;
                    }
                }
            }
        }
    }
}

// ============================================================================
// Flash attention. Br=128, Bc=64, 8 warps x 16 q-rows, 2 CTAs/SM.
// QK^T fp16 (Q frags in regs, K/V frags via ldmatrix.x4). log2-domain softmax
// with ex2.approx.f16x2; row sums via ones-MMA; P register-resident.
// (unchanged from R15)
// ============================================================================
#define QSW 36   // Q/K/V row stride in words (72 halves, 144 B)
#define Q_OFF  0
#define K_OFF  4608                    // + s*2304  (64*36)
#define V_OFF  11520                   // + s*2304
#define AT_WORDS 18432
#define AT_BYTES (AT_WORDS * 4)        // 73728 B

__global__ __launch_bounds__(256, 2) void attn_mma_kernel()
{
    extern __shared__ uint32_t smw[];
    int tid = threadIdx.x;
    int wid = tid >> 5, lane = tid & 31;
    int bh = blockIdx.y;
    int q0 = blockIdx.x * 128;

    const __half* QG = g_Qh + ((size_t)bh * SEQ + q0) * DH;
    const __half* KG = g_Kh + (size_t)bh * SEQ * DH;
    const __half* VG = g_Vh + (size_t)bh * SEQ * DH;   // [d][s]

    uint32_t smb = smem_u32(smw);

    int krow = tid >> 2, kc4 = tid & 3;
    auto load_kv = [&](int s, int kt) {
        const __half* kp = KG + ((size_t)kt * 64 + krow) * DH;
        const __half* vp = VG + (size_t)krow * SEQ + kt * 64;
#pragma unroll
        for (int q = 0; q < 2; q++) {
            int eo = kc4 * 16 + q * 8;
            CP_ASYNC16(smb + (K_OFF + s * 2304) * 4 + krow * 144 + kc4 * 32 + q * 16,
                       kp + eo);
            CP_ASYNC16(smb + (V_OFF + s * 2304) * 4 + krow * 144 + kc4 * 32 + q * 16,
                       vp + eo);
        }
    };

    // group 0: Q tile + KV tile 0
    {
        int row = tid >> 1, half = (tid & 1);
#pragma unroll
        for (int q = 0; q < 4; q++) {
            int eo = half * 32 + q * 8;
            CP_ASYNC16(smb + Q_OFF * 4 + row * 144 + half * 64 + q * 16,
                       QG + row * DH + eo);
        }
    }
    load_kv(0, 0);
    CP_COMMIT;
    load_kv(1, 1);
    CP_COMMIT;

    int r0 = wid * 16 + (lane >> 2);  // query row (first half)
    int kq = lane & 3;

    // ldmatrix lane addresses for K/V fragments (base, slot 0)
    int lrow = lane & 7, lt = lane >> 3;
    uint32_t kA[4], vA[4];
#pragma unroll
    for (int g = 0; g < 4; g++) {
        uint32_t roff = (g * 16 + lrow + (lt >> 1) * 8) * 144 + (lt & 1) * 16;
        kA[g] = smb + K_OFF * 4 + roff;
        vA[g] = smb + V_OFF * 4 + roff;
    }

    // ---- hoist Q fragments to registers ----
    CP_WAIT1;
    __syncthreads();
    uint32_t qf[4][4];
    const uint32_t* Qs = smw + Q_OFF;
#pragma unroll
    for (int ks = 0; ks < 4; ks++) {
        qf[ks][0] = Qs[r0 * QSW + ks * 8 + kq];
        qf[ks][1] = Qs[(r0 + 8) * QSW + ks * 8 + kq];
        qf[ks][2] = Qs[r0 * QSW + ks * 8 + kq + 4];
        qf[ks][3] = Qs[(r0 + 8) * QSW + ks * 8 + kq + 4];
    }

    // running max in log2 units: M = m * log2e; score coeff folds 1/8 * log2e
    const float c1 = 0.18033688011112042f;   // 0.125 * log2(e)
    float M0v = -INFINITY, M1v = -INFINITY, l0v = 0.f, l1v = 0.f;
    float o[8][4];
#pragma unroll
    for (int nt = 0; nt < 8; nt++)
#pragma unroll
        for (int j = 0; j < 4; j++) o[nt][j] = 0.f;

    for (int kt = 0; kt < SEQ / 64; kt++) {
        int s = kt % 3;
        uint32_t so = s * 9216;    // slot byte offset (2304 words)
        CP_WAIT1;
        __syncthreads();
        if (kt + 2 < SEQ / 64) load_kv((kt + 2) % 3, kt + 2);
        CP_COMMIT;

        // ---- S = Q K^T (fp16, K frags via ldmatrix) ----
        float sc[8][4];
#pragma unroll
        for (int nt = 0; nt < 8; nt++)
#pragma unroll
            for (int j = 0; j < 4; j++) sc[nt][j] = 0.f;
#pragma unroll
        for (int ks = 0; ks < 4; ks++) {
            uint32_t kbb = so + ks * 32;
#pragma unroll
            for (int g = 0; g < 4; g++) {
                uint32_t bf0, bf1, bf2, bf3;
                LDSM_X4(bf0, bf1, bf2, bf3, kA[g] + kbb);
                mma_f16(sc[2 * g],     qf[ks][0], qf[ks][1], qf[ks][2], qf[ks][3], bf0, bf1);
                mma_f16(sc[2 * g + 1], qf[ks][0], qf[ks][1], qf[ks][2], qf[ks][3], bf2, bf3);
            }
        }

        // ---- softmax (log2 domain), P -> fp16x2 via ex2.approx.f16x2 ----
        float mx0 = sc[0][0], mx1 = sc[0][2];
#pragma unroll
        for (int nt = 0; nt < 8; nt++) {
            mx0 = fmaxf(mx0, fmaxf(sc[nt][0], sc[nt][1]));
            mx1 = fmaxf(mx1, fmaxf(sc[nt][2], sc[nt][3]));
        }
        mx0 = fmaxf(mx0, __shfl_xor_sync(0xffffffffu, mx0, 1));
        mx0 = fmaxf(mx0, __shfl_xor_sync(0xffffffffu, mx0, 2));
        mx1 = fmaxf(mx1, __shfl_xor_sync(0xffffffffu, mx1, 1));
        mx1 = fmaxf(mx1, __shfl_xor_sync(0xffffffffu, mx1, 2));
        float Mn0 = fmaxf(M0v, mx0 * c1);
        float Mn1 = fmaxf(M1v, mx1 * c1);
        float alf0 = ex2f(M0v - Mn0), alf1 = ex2f(M1v - Mn1);
        M0v = Mn0; M1v = Mn1;
        uint32_t pa[4][4];
#pragma unroll
        for (int nt = 0; nt < 8; nt++) {
            float u0 = fmaf(sc[nt][0], c1, -Mn0);
            float u1 = fmaf(sc[nt][1], c1, -Mn0);
            float u2 = fmaf(sc[nt][2], c1, -Mn1);
            float u3 = fmaf(sc[nt][3], c1, -Mn1);
            int t = nt >> 1, hi = (nt & 1) * 2;
            pa[t][hi]     = ex2_h2(u0, u1);
            pa[t][hi + 1] = ex2_h2(u2, u3);
            o[nt][0] *= alf0; o[nt][1] *= alf0;
            o[nt][2] *= alf1; o[nt][3] *= alf1;
        }

        // ---- O += P V (V frags via ldmatrix) ; row sums via ones-MMA ----
        float lacc[4] = {0.f, 0.f, 0.f, 0.f};
#pragma unroll
        for (int t = 0; t < 4; t++) {
            uint32_t kbb = so + t * 32;
            mma_f16(lacc, pa[t][0], pa[t][1], pa[t][2], pa[t][3], H_ONES, H_ONES);
#pragma unroll
            for (int g = 0; g < 4; g++) {
                uint32_t bf0, bf1, bf2, bf3;
                LDSM_X4(bf0, bf1, bf2, bf3, vA[g] + kbb);
                mma_f16(o[2 * g],     pa[t][0], pa[t][1], pa[t][2], pa[t][3], bf0, bf1);
                mma_f16(o[2 * g + 1], pa[t][0], pa[t][1], pa[t][2], pa[t][3], bf2, bf3);
            }
        }
        l0v = l0v * alf0 + lacc[0];
        l1v = l1v * alf1 + lacc[2];
    }

    // ---- epilogue: normalize, fp16 for GEMM2, merge heads ----
    float inv0 = 1.f / l0v, inv1 = 1.f / l1v;
    int b = bh >> 4, h = bh & (NH - 1);
    int q = q0 + r0;
    __half* dst0 = g_Oh + ((size_t)(b * SEQ + q)) * DMODEL + h * DH;
    __half* dst1 = dst0 + 8 * DMODEL;
#pragma unroll
    for (int nt = 0; nt < 8; nt++) {
        int cb = nt * 8 + 2 * kq;
        *(uint32_t*)(dst0 + cb) = pack_h2(o[nt][0] * inv0, o[nt][1] * inv0);
        *(uint32_t*)(dst1 + cb) = pack_h2(o[nt][2] * inv1, o[nt][3] * inv1);
    }
}

// ---------------------------------------------------------------------------
extern "C" void kernel_launch(void* const* d_in, const int* in_sizes, int n_in,
                              void* d_out, int out_size) {
    (void)in_sizes; (void)n_in; (void)out_size;
    const float* x     = (const float*)d_in[0];
    const float* w_in  = (const float*)d_in[1];
    const float* b_in  = (const float*)d_in[2];
    const float* w_out = (const float*)d_in[3];
    const float* b_out = (const float*)d_in[4];
    float* out = (float*)d_out;

    cudaFuncSetAttribute(gemm_h_kernel,
                         cudaFuncAttributeMaxDynamicSharedMemorySize, GSM_BYTES);
    cudaFuncSetAttribute(attn_mma_kernel,
                         cudaFuncAttributeMaxDynamicSharedMemorySize, AT_BYTES);

    __half *gxh, *gw1t, *gw2t, *gOh;
    cudaGetSymbolAddress((void**)&gxh,  g_xh);
    cudaGetSymbolAddress((void**)&gw1t, g_w1t);
    cudaGetSymbolAddress((void**)&gw2t, g_w2t);
    cudaGetSymbolAddress((void**)&gOh,  g_Oh);

    // Pre: x -> fp16, weights -> transposed fp16
    {
        int n4 = ROWS * DMODEL / 4;
        cvt_h_kernel<<<(n4 + 255) / 256, 256>>>((const float4*)x, (uint2*)gxh, n4);
        transp_h_kernel<<<dim3(N_QKV / 32, DMODEL / 32), 256>>>(w_in, gw1t, DMODEL, N_QKV);
        transp_h_kernel<<<dim3(DMODEL / 32, DMODEL / 32), 256>>>(w_out, gw2t, DMODEL, DMODEL);
    }

    // GEMM1: QKV projection + scatter  (M=8192, N=3072)
    gemm_h_kernel<<<dim3(N_QKV / 128, ROWS / 128), 256, GSM_BYTES>>>(
        gxh, gw1t, b_in, nullptr, 0);
    // Attention: 16 q-tiles x 64 (b,h)
    attn_mma_kernel<<<dim3(SEQ / 128, B_SZ * NH), 256, AT_BYTES>>>();
    // GEMM2: output projection  (M=8192, N=1024)
    gemm_h_kernel<<<dim3(DMODEL / 128, ROWS / 128), 256, GSM_BYTES>>>(
        gOh, gw2t, b_out, out, 1);
}